// round 3
// baseline (speedup 1.0000x reference)
#include <cuda_runtime.h>
#include <cuda_bf16.h>
#include <math.h>

// Problem constants: B=4, S=4096, H=2048, E=8, K=2
#define T_TOKENS 16384
#define HDIM     2048
#define NEXP     8
#define TOPK     2
#define HV       (HDIM / 4)   // 512 16-byte vectors per row

// Packed f32x2 FMA: d = a*b + d (elementwise on packed pairs). PTX-only path.
#define FMA_F32X2(d, a, b) \
    asm("fma.rn.f32x2 %0, %1, %2, %0;" : "+l"(d) : "l"(a), "l"(b))

#define UNPACK_F32X2(lo, hi, in) \
    asm("mov.b64 {%0, %1}, %2;" : "=f"(lo), "=f"(hi) : "l"(in))

// Zero-initialized at module load; last block re-zeros after each use so
// every graph replay sees a clean state (deterministic).
__device__ int g_counts[NEXP];
__device__ unsigned int g_done;

// Transposed warp reduction: on entry every lane holds a[p] = partial sum for
// pair p (p = 0..31). On exit a[0] in lane L = total sum for pair L.
// 31 shfl + 31 add instead of 32x5 of each.
__device__ __forceinline__ void reduce_transpose32(float a[32], int lane) {
    #pragma unroll
    for (int off = 16; off > 0; off >>= 1) {
        const int up   = (lane & off) ? off : 0;   // arithmetic select, no branch
        const int keep = up;                        // up lanes keep high half
        const int send = off - up;                  // and send low half
        #pragma unroll
        for (int j = 0; j < 32; j++) {              // bounded by off at runtime
            if (j < off) {
                float other = __shfl_xor_sync(0xFFFFFFFFu, a[send + j], off);
                a[j] = a[keep + j] + other;
            }
        }
    }
}

// 256 CTAs x 256 threads = 2048 warps; each warp handles exactly 2 groups of
// 4 tokens (8 tokens). One resident wave at occupancy 2. Aux-loss finalize is
// fused via a last-block-done pattern (no separate launch).
__global__ __launch_bounds__(256, 2)
void router_kernel(const float* __restrict__ x,
                   const float* __restrict__ gate_w,
                   float* __restrict__ out) {
    __shared__ int s_counts[NEXP];
    if (threadIdx.x < NEXP) s_counts[threadIdx.x] = 0;
    __syncthreads();

    const int lane        = threadIdx.x & 31;
    const int warp_global = (blockIdx.x * blockDim.x + threadIdx.x) >> 5;

    const ulonglong2* __restrict__ x2 = (const ulonglong2*)x;   // 4 floats/elem
    const ulonglong2* __restrict__ w2 = (const ulonglong2*)gate_w;

    #pragma unroll 1
    for (int g2 = 0; g2 < 2; g2++) {
        const int t0 = (warp_global * 2 + g2) * 4;

        // Packed accumulators: acc[m][e] = (sum even idx, sum odd idx)
        unsigned long long acc[4][NEXP];
        #pragma unroll
        for (int m = 0; m < 4; m++)
            #pragma unroll
            for (int e = 0; e < NEXP; e++) acc[m][e] = 0ULL;

        #pragma unroll 2
        for (int i = lane; i < HV; i += 32) {
            ulonglong2 xv[4];
            #pragma unroll
            for (int m = 0; m < 4; m++)
                xv[m] = __ldg(x2 + (size_t)(t0 + m) * HV + i);

            #pragma unroll
            for (int e = 0; e < NEXP; e++) {
                ulonglong2 wv = __ldg(w2 + (size_t)e * HV + i);
                #pragma unroll
                for (int m = 0; m < 4; m++) {
                    FMA_F32X2(acc[m][e], xv[m].x, wv.x);
                    FMA_F32X2(acc[m][e], xv[m].y, wv.y);
                }
            }
        }

        // Collapse packed pairs into 32 scalars indexed by pair p = m*8+e.
        float a[32];
        #pragma unroll
        for (int m = 0; m < 4; m++)
            #pragma unroll
            for (int e = 0; e < NEXP; e++) {
                float lo, hi;
                UNPACK_F32X2(lo, hi, acc[m][e]);
                a[m * NEXP + e] = lo + hi;
            }

        reduce_transpose32(a, lane);   // lane L now holds logit for pair L

        // Gather this token-group's 8 logits into every lane of its octet.
        const int m  = lane >> 3;      // token within group for this lane
        float l[NEXP];
        #pragma unroll
        for (int e = 0; e < NEXP; e++)
            l[e] = __shfl_sync(0xFFFFFFFFu, a[0], (m << 3) | e);

        if ((lane & 7) == 0) {
            const int t = t0 + m;

            // top-1 (strict > keeps lowest index on tie, matching jax top_k)
            float m1 = l[0]; int i1 = 0;
            #pragma unroll
            for (int e = 1; e < NEXP; e++)
                if (l[e] > m1) { m1 = l[e]; i1 = e; }
            // top-2
            float m2 = -INFINITY; int i2 = 0;
            #pragma unroll
            for (int e = 0; e < NEXP; e++)
                if (e != i1 && l[e] > m2) { m2 = l[e]; i2 = e; }

            // renormalized top-2 softmax weights
            float e2  = __expf(m2 - m1);    // <= 1, numerically safe
            float inv = 1.0f / (1.0f + e2);

            out[(size_t)t * TOPK + 0] = inv;
            out[(size_t)t * TOPK + 1] = e2 * inv;
            out[(size_t)T_TOKENS * TOPK + (size_t)t * TOPK + 0] = (float)i1;
            out[(size_t)T_TOKENS * TOPK + (size_t)t * TOPK + 1] = (float)i2;

            atomicAdd(&s_counts[i1], 1);
            atomicAdd(&s_counts[i2], 1);
        }
    }

    __syncthreads();
    if (threadIdx.x < NEXP)
        atomicAdd(&g_counts[threadIdx.x], s_counts[threadIdx.x]);
    __threadfence();
    __syncthreads();

    // Last block computes the aux loss and resets global state.
    if (threadIdx.x == 0) {
        unsigned int prev = atomicAdd(&g_done, 1u);
        if (prev == gridDim.x - 1) {
            volatile int* vc = (volatile int*)g_counts;
            float mpe[NEXP];
            float mu = 0.0f;
            #pragma unroll
            for (int e = 0; e < NEXP; e++) {
                mpe[e] = (float)vc[e] / (float)T_TOKENS;
                mu += mpe[e];
            }
            mu *= (1.0f / NEXP);
            float v = 0.0f;
            #pragma unroll
            for (int e = 0; e < NEXP; e++) {
                float d = mpe[e] - mu;
                v += d * d;
            }
            v *= (1.0f / (NEXP - 1));   // unbiased variance (ddof=1)
            out[(size_t)T_TOKENS * TOPK * 2] = v * (float)NEXP;

            // Reset for the next graph replay.
            #pragma unroll
            for (int e = 0; e < NEXP; e++) g_counts[e] = 0;
            g_done = 0u;
        }
    }
}

extern "C" void kernel_launch(void* const* d_in, const int* in_sizes, int n_in,
                              void* d_out, int out_size) {
    const float* x      = (const float*)d_in[0];   // (B,S,H) = (T, H)
    const float* gate_w = (const float*)d_in[1];   // (E, H)
    float* out = (float*)d_out;

    router_kernel<<<256, 256>>>(x, gate_w, out);
}

// round 4
// speedup vs baseline: 1.0215x; 1.0215x over previous
#include <cuda_runtime.h>
#include <cuda_bf16.h>
#include <math.h>

// Problem constants: B=4, S=4096, H=2048, E=8, K=2
#define T_TOKENS 16384
#define HDIM     2048
#define NEXP     8
#define TOPK     2
#define H4       (HDIM / 4)   // 512 float4 per row

// Zero-initialized at module load; last block re-zeros after each use so
// every graph replay sees a clean state (deterministic).
__device__ int g_counts[NEXP];
__device__ unsigned int g_done;

// One warp = one group of 4 tokens; lanes split H, butterfly reduce at end.
// 1024 CTAs x 128 threads = 4096 warps = T/4 groups, all resident in ONE wave
// at 8 CTAs/SM (64-reg budget). Aux loss fused via last-block pattern.
__global__ __launch_bounds__(128, 8)
void router_kernel(const float* __restrict__ x,
                   const float* __restrict__ gate_w,
                   float* __restrict__ out) {
    __shared__ int s_counts[NEXP];
    if (threadIdx.x < NEXP) s_counts[threadIdx.x] = 0;
    __syncthreads();

    const int lane        = threadIdx.x & 31;
    const int warp_global = (blockIdx.x * blockDim.x + threadIdx.x) >> 5;
    const int t0          = warp_global * 4;

    const float4* __restrict__ x4 = (const float4*)x;
    const float4* __restrict__ w4 = (const float4*)gate_w;

    float acc[4][NEXP];
    #pragma unroll
    for (int m = 0; m < 4; m++)
        #pragma unroll
        for (int e = 0; e < NEXP; e++) acc[m][e] = 0.0f;

    // 16 iterations; 12 independent LDG.128 per iteration (4 x + 8 w) give
    // the MLP; 32 warps/SM hide DRAM latency.
    for (int i = lane; i < H4; i += 32) {
        float4 xv[4];
        #pragma unroll
        for (int m = 0; m < 4; m++)
            xv[m] = __ldg(x4 + (size_t)(t0 + m) * H4 + i);

        #pragma unroll
        for (int e = 0; e < NEXP; e++) {
            float4 wv = __ldg(w4 + (size_t)e * H4 + i);
            #pragma unroll
            for (int m = 0; m < 4; m++) {
                acc[m][e] = fmaf(xv[m].x, wv.x, acc[m][e]);
                acc[m][e] = fmaf(xv[m].y, wv.y, acc[m][e]);
                acc[m][e] = fmaf(xv[m].z, wv.z, acc[m][e]);
                acc[m][e] = fmaf(xv[m].w, wv.w, acc[m][e]);
            }
        }
    }

    // Butterfly-reduce all 32 accumulators across the warp (static indexing).
    #pragma unroll
    for (int m = 0; m < 4; m++)
        #pragma unroll
        for (int e = 0; e < NEXP; e++)
            #pragma unroll
            for (int off = 16; off > 0; off >>= 1)
                acc[m][e] += __shfl_xor_sync(0xFFFFFFFFu, acc[m][e], off);

    // Lanes 0..3 each finish one token (every lane holds the full sums).
    if (lane < 4) {
        const int t = t0 + lane;
        float l[NEXP];
        #pragma unroll
        for (int e = 0; e < NEXP; e++) l[e] = acc[lane][e];

        // top-1 (strict > keeps lowest index on tie, matching jax top_k)
        float m1 = l[0]; int i1 = 0;
        #pragma unroll
        for (int e = 1; e < NEXP; e++)
            if (l[e] > m1) { m1 = l[e]; i1 = e; }
        // top-2
        float m2 = -INFINITY; int i2 = 0;
        #pragma unroll
        for (int e = 0; e < NEXP; e++)
            if (e != i1 && l[e] > m2) { m2 = l[e]; i2 = e; }

        // renormalized top-2 softmax weights
        float e2  = __expf(m2 - m1);    // <= 1, numerically safe
        float inv = 1.0f / (1.0f + e2);

        out[(size_t)t * TOPK + 0] = inv;
        out[(size_t)t * TOPK + 1] = e2 * inv;
        out[(size_t)T_TOKENS * TOPK + (size_t)t * TOPK + 0] = (float)i1;
        out[(size_t)T_TOKENS * TOPK + (size_t)t * TOPK + 1] = (float)i2;

        atomicAdd(&s_counts[i1], 1);
        atomicAdd(&s_counts[i2], 1);
    }

    __syncthreads();
    if (threadIdx.x < NEXP)
        atomicAdd(&g_counts[threadIdx.x], s_counts[threadIdx.x]);
    __threadfence();
    __syncthreads();

    // Last block computes the aux loss and resets global state.
    if (threadIdx.x == 0) {
        unsigned int prev = atomicAdd(&g_done, 1u);
        if (prev == gridDim.x - 1) {
            volatile int* vc = (volatile int*)g_counts;
            float mpe[NEXP];
            float mu = 0.0f;
            #pragma unroll
            for (int e = 0; e < NEXP; e++) {
                mpe[e] = (float)vc[e] / (float)T_TOKENS;
                mu += mpe[e];
            }
            mu *= (1.0f / NEXP);
            float v = 0.0f;
            #pragma unroll
            for (int e = 0; e < NEXP; e++) {
                float d = mpe[e] - mu;
                v += d * d;
            }
            v *= (1.0f / (NEXP - 1));   // unbiased variance (ddof=1)
            out[(size_t)T_TOKENS * TOPK * 2] = v * (float)NEXP;

            // Reset for the next graph replay.
            #pragma unroll
            for (int e = 0; e < NEXP; e++) g_counts[e] = 0;
            g_done = 0u;
        }
    }
}

extern "C" void kernel_launch(void* const* d_in, const int* in_sizes, int n_in,
                              void* d_out, int out_size) {
    const float* x      = (const float*)d_in[0];   // (B,S,H) = (T, H)
    const float* gate_w = (const float*)d_in[1];   // (E, H)
    float* out = (float*)d_out;

    router_kernel<<<1024, 128>>>(x, gate_w, out);
}

// round 5
// speedup vs baseline: 1.1702x; 1.1455x over previous
#include <cuda_runtime.h>
#include <cuda_bf16.h>
#include <math.h>

// Problem constants: B=4, S=4096, H=2048, E=8, K=2
#define T_TOKENS 16384
#define HDIM     2048
#define NEXP     8
#define TOPK     2
#define H4       (HDIM / 4)   // 512 float4 per row
#define TPW      8            // tokens per warp

// Zero-initialized at module load; last block re-zeros after each use so
// every graph replay sees a clean state (deterministic).
__device__ int g_counts[NEXP];
__device__ unsigned int g_done;

// One warp = 8 tokens; lanes split H. 512 CTAs x 128 threads = 2048 warps =
// T/8 groups, all resident in ONE wave at 4 CTAs/SM. Each gate_w read is
// amortized over 8 tokens (halves L1 wavefront demand vs 4-token version).
__global__ __launch_bounds__(128, 4)
void router_kernel(const float* __restrict__ x,
                   const float* __restrict__ gate_w,
                   float* __restrict__ out) {
    __shared__ int s_counts[NEXP];
    if (threadIdx.x < NEXP) s_counts[threadIdx.x] = 0;
    __syncthreads();

    const int lane        = threadIdx.x & 31;
    const int warp_global = (blockIdx.x * blockDim.x + threadIdx.x) >> 5;
    const int t0          = warp_global * TPW;

    const float4* __restrict__ x4 = (const float4*)x;
    const float4* __restrict__ w4 = (const float4*)gate_w;

    // a[tok*8 + exp] accumulators (64 regs)
    float a[TPW * NEXP];
    #pragma unroll
    for (int p = 0; p < TPW * NEXP; p++) a[p] = 0.0f;

    for (int i = lane; i < H4; i += 32) {
        float4 xv[TPW];
        #pragma unroll
        for (int m = 0; m < TPW; m++)
            xv[m] = __ldg(x4 + (size_t)(t0 + m) * H4 + i);

        #pragma unroll
        for (int e = 0; e < NEXP; e++) {
            float4 wv = __ldg(w4 + (size_t)e * H4 + i);
            #pragma unroll
            for (int m = 0; m < TPW; m++) {
                a[m * NEXP + e] = fmaf(xv[m].x, wv.x, a[m * NEXP + e]);
                a[m * NEXP + e] = fmaf(xv[m].y, wv.y, a[m * NEXP + e]);
                a[m * NEXP + e] = fmaf(xv[m].z, wv.z, a[m * NEXP + e]);
                a[m * NEXP + e] = fmaf(xv[m].w, wv.w, a[m * NEXP + e]);
            }
        }
    }

    // Halving warp reduction over 64 partial sums. All array indices are
    // compile-time constants; lane-dependence is in VALUE selects only.
    // After 5 levels, lane L holds a[0]=sum(group 2L), a[1]=sum(group 2L+1),
    // where group = tok*8 + exp.
#define RED_LEVEL(O, L2)                                                   \
    _Pragma("unroll")                                                      \
    for (int j = 0; j < (L2); j++) {                                       \
        float mine  = (lane & (O)) ? a[j + (L2)] : a[j];                   \
        float yours = (lane & (O)) ? a[j] : a[j + (L2)];                   \
        a[j] = mine + __shfl_xor_sync(0xFFFFFFFFu, yours, (O));            \
    }
    RED_LEVEL(16, 32)
    RED_LEVEL(8, 16)
    RED_LEVEL(4, 8)
    RED_LEVEL(2, 4)
    RED_LEVEL(1, 2)
#undef RED_LEVEL

    // Quad gather: lanes 4q..4q+3 hold token q's 8 logits (2 each, experts
    // 2(lane&3) and 2(lane&3)+1). Rebuild l[8] in every lane for its token.
    const int tok = lane >> 2;
    float l[NEXP];
    #pragma unroll
    for (int q = 0; q < 4; q++) {
        l[2 * q]     = __shfl_sync(0xFFFFFFFFu, a[0], (tok << 2) | q);
        l[2 * q + 1] = __shfl_sync(0xFFFFFFFFu, a[1], (tok << 2) | q);
    }

    if ((lane & 3) == 0) {
        const int t = t0 + tok;

        // top-1 (strict > keeps lowest index on tie, matching jax top_k)
        float m1 = l[0]; int i1 = 0;
        #pragma unroll
        for (int e = 1; e < NEXP; e++)
            if (l[e] > m1) { m1 = l[e]; i1 = e; }
        // top-2
        float m2 = -INFINITY; int i2 = 0;
        #pragma unroll
        for (int e = 0; e < NEXP; e++)
            if (e != i1 && l[e] > m2) { m2 = l[e]; i2 = e; }

        // renormalized top-2 softmax weights
        float e2  = __expf(m2 - m1);    // <= 1, numerically safe
        float inv = 1.0f / (1.0f + e2);

        out[(size_t)t * TOPK + 0] = inv;
        out[(size_t)t * TOPK + 1] = e2 * inv;
        out[(size_t)T_TOKENS * TOPK + (size_t)t * TOPK + 0] = (float)i1;
        out[(size_t)T_TOKENS * TOPK + (size_t)t * TOPK + 1] = (float)i2;

        atomicAdd(&s_counts[i1], 1);
        atomicAdd(&s_counts[i2], 1);
    }

    __syncthreads();
    if (threadIdx.x < NEXP)
        atomicAdd(&g_counts[threadIdx.x], s_counts[threadIdx.x]);
    __threadfence();
    __syncthreads();

    // Last block computes the aux loss and resets global state.
    if (threadIdx.x == 0) {
        unsigned int prev = atomicAdd(&g_done, 1u);
        if (prev == gridDim.x - 1) {
            volatile int* vc = (volatile int*)g_counts;
            float mpe[NEXP];
            float mu = 0.0f;
            #pragma unroll
            for (int e = 0; e < NEXP; e++) {
                mpe[e] = (float)vc[e] / (float)T_TOKENS;
                mu += mpe[e];
            }
            mu *= (1.0f / NEXP);
            float v = 0.0f;
            #pragma unroll
            for (int e = 0; e < NEXP; e++) {
                float d = mpe[e] - mu;
                v += d * d;
            }
            v *= (1.0f / (NEXP - 1));   // unbiased variance (ddof=1)
            out[(size_t)T_TOKENS * TOPK * 2] = v * (float)NEXP;

            // Reset for the next graph replay.
            #pragma unroll
            for (int e = 0; e < NEXP; e++) g_counts[e] = 0;
            g_done = 0u;
        }
    }
}

extern "C" void kernel_launch(void* const* d_in, const int* in_sizes, int n_in,
                              void* d_out, int out_size) {
    const float* x      = (const float*)d_in[0];   // (B,S,H) = (T, H)
    const float* gate_w = (const float*)d_in[1];   // (E, H)
    float* out = (float*)d_out;

    router_kernel<<<512, 128>>>(x, gate_w, out);
}